// round 4
// baseline (speedup 1.0000x reference)
#include <cuda_runtime.h>
#include <cstdint>
#include <cstddef>

// ---------------------------------------------------------------------------
// 2-layer GCN. CSR (counting-sort by dst, ranges padded to 4) aggregation,
// f32x2 packed-FFMA GEMMs, no feature atomics.
// out[v] = sum_{e: dst=v} norm[e]*h[src] + dinv[v]^2*h[v] (+bias)
// ---------------------------------------------------------------------------

#define N_MAX 100000
#define E_MAX 1200000
#define EP_MAX (E_MAX + 3 * N_MAX)      // padded edge capacity

__device__ __align__(256) float g_deg  [N_MAX];
__device__ __align__(256) int   g_cnt  [N_MAX];
__device__ __align__(256) float g_dinv [N_MAX];
__device__ __align__(256) int   g_ptr  [N_MAX + 1];
__device__ __align__(256) int   g_src  [E_MAX];
__device__ __align__(256) int   g_dst  [E_MAX];
__device__ __align__(256) int   g_rank [E_MAX];
__device__ __align__(256) int   g_srcs [EP_MAX];   // dst-sorted src (pad: 0)
__device__ __align__(256) float g_norms[EP_MAX];   // dst-sorted norm (pad: 0)
__device__ __align__(256) float g_h1  [(size_t)N_MAX * 64];
__device__ __align__(256) float g_agg1[(size_t)N_MAX * 64];
__device__ __align__(256) float g_h2  [(size_t)N_MAX * 32];
__device__ __align__(256) int   g_bsum[128];
__device__ __align__(256) int   g_boff[130];
__device__ int g_is32;

// ---------------------------------------------------------------------------
__global__ void zero_kernel(int n, int ep) {
    int i = blockIdx.x * blockDim.x + threadIdx.x;
    if (i < n) { g_deg[i] = 0.0f; g_cnt[i] = 0; }
    if (i < ep) { g_srcs[i] = 0; g_norms[i] = 0.0f; }
    if (i == 0) g_is32 = 0;
}

// Read buffer as int64; any value outside [0,n) => data is int32.
__global__ void detect_kernel(const long long* __restrict__ ei64, int e, int n) {
    int i = blockIdx.x * blockDim.x + threadIdx.x;
    int bad = 0;
    if (i < e) {
        long long v = ei64[i];
        bad = ((unsigned long long)v >= (unsigned long long)n) ? 1 : 0;
    }
    unsigned m = __ballot_sync(0xFFFFFFFFu, bad);
    if (m && (threadIdx.x & 31) == (__ffs(m) - 1)) atomicOr(&g_is32, 1);
}

// Decode indices, weighted in-degree, per-dst rank (for sort placement).
__global__ void edge_prep_kernel(const void* __restrict__ ei,
                                 const float* __restrict__ ew, int e, int n) {
    int i = blockIdx.x * blockDim.x + threadIdx.x;
    if (i >= e) return;
    int s, d;
    if (g_is32) {
        const int* p = (const int*)ei;
        s = p[i]; d = p[(size_t)e + i];
    } else {
        const long long* p = (const long long*)ei;
        s = (int)p[i]; d = (int)p[(size_t)e + i];
    }
    if ((unsigned)s >= (unsigned)n) s = 0;
    if ((unsigned)d >= (unsigned)n) d = 0;
    g_src[i] = s;
    g_dst[i] = d;
    g_rank[i] = atomicAdd(&g_cnt[d], 1);
    atomicAdd(&g_deg[d], ew[i]);
}

// ------- exclusive scan of padded counts -> g_ptr, fused dinv --------------
__global__ void scan1_kernel(int n) {             // 256 thr, 1024 nodes/block
    __shared__ int wsum[8];
    int b = blockIdx.x, t = threadIdx.x;
    int base = b * 1024 + t * 4;
    int c[4];
#pragma unroll
    for (int j = 0; j < 4; j++) {
        int idx = base + j;
        if (idx < n) {
            c[j] = (g_cnt[idx] + 3) & ~3;                 // pad to 4
            g_dinv[idx] = rsqrtf(1.0f + g_deg[idx]);      // deg >= 1 always
        } else c[j] = 0;
    }
    int tsum = c[0] + c[1] + c[2] + c[3];
    int lane = t & 31, w = t >> 5;
    int v = tsum;
#pragma unroll
    for (int off = 1; off < 32; off <<= 1) {
        int u = __shfl_up_sync(~0u, v, off); if (lane >= off) v += u;
    }
    if (lane == 31) wsum[w] = v;
    __syncthreads();
    if (w == 0) {
        int s = (lane < 8) ? wsum[lane] : 0;
#pragma unroll
        for (int off = 1; off < 8; off <<= 1) {
            int u = __shfl_up_sync(~0u, s, off); if (lane >= off) s += u;
        }
        if (lane < 8) wsum[lane] = s;
    }
    __syncthreads();
    int excl = v - tsum + ((w > 0) ? wsum[w - 1] : 0);
    int run = excl;
#pragma unroll
    for (int j = 0; j < 4; j++) { int idx = base + j; if (idx < n) g_ptr[idx] = run; run += c[j]; }
    if (t == 255) g_bsum[b] = excl + tsum;
}

__global__ void scan2_kernel(int nb) {            // single block, 128 thr
    __shared__ int sh[4];
    int t = threadIdx.x;
    int v = (t < nb) ? g_bsum[t] : 0;
    int lane = t & 31, w = t >> 5;
    int s = v;
#pragma unroll
    for (int off = 1; off < 32; off <<= 1) {
        int u = __shfl_up_sync(~0u, s, off); if (lane >= off) s += u;
    }
    if (lane == 31) sh[w] = s;
    __syncthreads();
    if (w == 0) {
        int x = (lane < 4) ? sh[lane] : 0;
#pragma unroll
        for (int off = 1; off < 4; off <<= 1) {
            int u = __shfl_up_sync(~0u, x, off); if (lane >= off) x += u;
        }
        if (lane < 4) sh[lane] = x;
    }
    __syncthreads();
    int excl = s - v + ((w > 0) ? sh[w - 1] : 0);
    if (t < nb) g_boff[t] = excl;
    if (t == nb - 1) g_boff[nb] = excl + v;       // total padded edges
}

__global__ void scan3_kernel(int n, int nscan) {
    int i = blockIdx.x * blockDim.x + threadIdx.x;
    if (i < n) g_ptr[i] += g_boff[i >> 10];
    if (i == n) g_ptr[n] = g_boff[nscan];
}

// scatter edges into sorted order; fuses norm computation (no atomic).
__global__ void fill_kernel(const float* __restrict__ ew, int e) {
    int i = blockIdx.x * blockDim.x + threadIdx.x;
    if (i >= e) return;
    int s = g_src[i], d = g_dst[i];
    int pos = g_ptr[d] + g_rank[i];
    g_srcs[pos] = s;
    g_norms[pos] = g_dinv[s] * ew[i] * g_dinv[d];
}

// ---------------------------------------------------------------------------
// GEMM: H = f(X) @ W  (CIN=64) with packed f32x2 FFMA.
// ---------------------------------------------------------------------------
typedef unsigned long long u64t;
__device__ __forceinline__ u64t pack2(float lo, float hi) {
    u64t r; asm("mov.b64 %0, {%1, %2};" : "=l"(r) : "f"(lo), "f"(hi)); return r;
}
__device__ __forceinline__ void ffma2(u64t& d, u64t a, u64t b) {
    asm("fma.rn.f32x2 %0, %1, %2, %0;" : "+l"(d) : "l"(a), "l"(b));
}
__device__ __forceinline__ float2 unpack2(u64t v) {
    float2 f; asm("mov.b64 {%0, %1}, %2;" : "=f"(f.x), "=f"(f.y) : "l"(v)); return f;
}

template<int LAYER>
__global__ __launch_bounds__(128)
void gemm_kernel(const float* __restrict__ Xext,
                 const float* __restrict__ Wm,
                 const float* __restrict__ bin, int n) {
    constexpr int COUT = (LAYER == 1) ? 64 : 32;
    constexpr int ROWS = (LAYER == 1) ? 32 : 64;
    constexpr int CIN  = 64;
    constexpr int CG   = COUT / 4;
    constexpr int NT   = 128;
    constexpr int XPAD = 68;

    const float* X = (LAYER == 1) ? Xext : g_agg1;
    float*       H = (LAYER == 1) ? g_h1 : g_h2;

    __shared__ float Ws[CIN * COUT];
    __shared__ float xs[ROWS * XPAD];

    const int tid  = threadIdx.x;
    const int row0 = blockIdx.x * ROWS;

    for (int i = tid * 4; i < CIN * COUT; i += NT * 4)
        *(float4*)(Ws + i) = *(const float4*)(Wm + i);

    for (int i = tid; i < ROWS * (CIN / 4); i += NT) {
        int r  = i >> 4;
        int c4 = i & 15;
        int gr = row0 + r;
        float4 v = make_float4(0.f, 0.f, 0.f, 0.f);
        if (gr < n) {
            v = *(const float4*)(X + (size_t)gr * CIN + c4 * 4);
            if (LAYER == 2) {
                float4 b = *(const float4*)(bin + c4 * 4);
                v.x = fmaxf(v.x + b.x, 0.f);
                v.y = fmaxf(v.y + b.y, 0.f);
                v.z = fmaxf(v.z + b.z, 0.f);
                v.w = fmaxf(v.w + b.w, 0.f);
            }
        }
        *(float4*)(xs + r * XPAD + c4 * 4) = v;
    }
    __syncthreads();

    const int jg = tid % CG;
    const int rg = tid / CG;
    const int j0 = jg * 4;
    const int r0 = rg * 4;

    u64t acc[4][2] = {};
#pragma unroll
    for (int k = 0; k < CIN; ++k) {
        const u64t* wp = (const u64t*)(Ws + k * COUT + j0);
        u64t w01 = wp[0];
        u64t w23 = wp[1];
#pragma unroll
        for (int r = 0; r < 4; ++r) {
            float xv = xs[(r0 + r) * XPAD + k];
            u64t xx = pack2(xv, xv);
            ffma2(acc[r][0], xx, w01);
            ffma2(acc[r][1], xx, w23);
        }
    }

#pragma unroll
    for (int r = 0; r < 4; ++r) {
        int gr = row0 + r0 + r;
        if (gr >= n) continue;
        float2 a0 = unpack2(acc[r][0]);
        float2 a1 = unpack2(acc[r][1]);
        *(float4*)(H + (size_t)gr * COUT + j0) =
            make_float4(a0.x, a0.y, a1.x, a1.y);
    }
}

// ---------------------------------------------------------------------------
// CSR aggregation. Ranges are 4-padded (pad entries: src=0, norm=0), so the
// inner loop is a pure 4-wide vector loop: int4+float4 index loads (aligned),
// 4 independent gathers (MLP=4), no tail.
// ---------------------------------------------------------------------------
template<int LAYER>
__global__ __launch_bounds__(256)
void csr_agg_kernel(const float* __restrict__ bias, float* __restrict__ AGGext, int n) {
    constexpr int C4 = (LAYER == 1) ? 16 : 8;
    const float4* __restrict__ H = (const float4*)((LAYER == 1) ? g_h1 : g_h2);
    float4* AGG = (LAYER == 1) ? (float4*)g_agg1 : (float4*)AGGext;

    int gi = blockIdx.x * blockDim.x + threadIdx.x;
    int v = gi / C4;
    int c = gi % C4;
    if (v >= n) return;

    int p0 = g_ptr[v], p1 = g_ptr[v + 1];

    float4 a0 = make_float4(0.f, 0.f, 0.f, 0.f);
    float4 a1 = make_float4(0.f, 0.f, 0.f, 0.f);
    for (int k = p0; k < p1; k += 4) {
        int4   ss = *(const int4*)(g_srcs + k);
        float4 nn = *(const float4*)(g_norms + k);
        float4 h0 = __ldg(&H[(size_t)ss.x * C4 + c]);
        float4 h1 = __ldg(&H[(size_t)ss.y * C4 + c]);
        float4 h2 = __ldg(&H[(size_t)ss.z * C4 + c]);
        float4 h3 = __ldg(&H[(size_t)ss.w * C4 + c]);
        a0.x += nn.x * h0.x; a0.y += nn.x * h0.y; a0.z += nn.x * h0.z; a0.w += nn.x * h0.w;
        a1.x += nn.y * h1.x; a1.y += nn.y * h1.y; a1.z += nn.y * h1.z; a1.w += nn.y * h1.w;
        a0.x += nn.z * h2.x; a0.y += nn.z * h2.y; a0.z += nn.z * h2.z; a0.w += nn.z * h2.w;
        a1.x += nn.w * h3.x; a1.y += nn.w * h3.y; a1.z += nn.w * h3.z; a1.w += nn.w * h3.w;
    }

    float dv  = g_dinv[v];
    float dv2 = dv * dv;
    float4 hv = __ldg(&H[(size_t)v * C4 + c]);
    float4 r;
    r.x = a0.x + a1.x + dv2 * hv.x;
    r.y = a0.y + a1.y + dv2 * hv.y;
    r.z = a0.z + a1.z + dv2 * hv.z;
    r.w = a0.w + a1.w + dv2 * hv.w;
    if (LAYER == 2) {
        float4 b = ((const float4*)bias)[c];
        r.x += b.x; r.y += b.y; r.z += b.z; r.w += b.w;
    }
    AGG[(size_t)v * C4 + c] = r;
}

// ---------------------------------------------------------------------------
extern "C" void kernel_launch(void* const* d_in, const int* in_sizes, int n_in,
                              void* d_out, int out_size) {
    const float* x   = (const float*)d_in[0];
    const void*  ei  = d_in[1];
    const float* ew  = (const float*)d_in[2];
    const float* W1  = (const float*)d_in[3];
    const float* b1  = (const float*)d_in[4];
    const float* W2  = (const float*)d_in[5];
    const float* b2  = (const float*)d_in[6];
    float*       out = (float*)d_out;

    const int n = in_sizes[0] / 64;
    const int e = in_sizes[2];
    const int ep = e + 3 * n;              // padded capacity to zero

    const int T = 256;
    const int nb_e  = (e + T - 1) / T;
    const int nb_z  = (ep + T - 1) / T;
    const int nscan = (n + 1023) / 1024;

    zero_kernel<<<nb_z, T>>>(n, ep);
    detect_kernel<<<nb_e, T>>>((const long long*)ei, e, n);
    edge_prep_kernel<<<nb_e, T>>>(ei, ew, e, n);
    scan1_kernel<<<nscan, 256>>>(n);
    scan2_kernel<<<1, 128>>>(nscan);
    scan3_kernel<<<(n + T) / T, T>>>(n, nscan);
    fill_kernel<<<nb_e, T>>>(ew, e);

    gemm_kernel<1><<<(n + 31) / 32, 128>>>(x, W1, nullptr, n);
    csr_agg_kernel<1><<<(n * 16 + T - 1) / T, T>>>(nullptr, nullptr, n);
    gemm_kernel<2><<<(n + 63) / 64, 128>>>(nullptr, W2, b1, n);
    csr_agg_kernel<2><<<(n * 8 + T - 1) / T, T>>>(b2, out, n);
}

// round 5
// speedup vs baseline: 1.2589x; 1.2589x over previous
#include <cuda_runtime.h>
#include <cuda_fp16.h>
#include <cstdint>
#include <cstddef>

// ---------------------------------------------------------------------------
// 2-layer GCN. CSR (counting-sort by dst, 4-padded ranges). fp16 gather path,
// fp32 accumulation seeded with exact self-loop term in the GEMM epilogue.
// out[v] = sum_{e: dst=v} norm[e]*h[src] + dinv[v]^2*h[v] (+bias)
// ---------------------------------------------------------------------------

#define N_MAX 100000
#define E_MAX 1200000
#define EP_MAX (E_MAX + 3 * N_MAX)

__device__ __align__(256) float  g_deg  [N_MAX];
__device__ __align__(256) int    g_cnt  [N_MAX];
__device__ __align__(256) float  g_dinv [N_MAX];
__device__ __align__(256) int    g_ptr  [N_MAX + 1];
__device__ __align__(256) int    g_src  [E_MAX];
__device__ __align__(256) int    g_dst  [E_MAX];
__device__ __align__(256) int    g_rank [E_MAX];
__device__ __align__(256) int    g_srcs [EP_MAX];   // dst-sorted src (pad: 0)
__device__ __align__(256) float  g_norms[EP_MAX];   // dst-sorted norm (pad: 0)
__device__ __align__(256) __half g_h1h [(size_t)N_MAX * 64];  // fp16 gather copy
__device__ __align__(256) __half g_h2h [(size_t)N_MAX * 32];
__device__ __align__(256) float  g_agg1[(size_t)N_MAX * 64];  // fp32 accumulator
__device__ __align__(256) int    g_bsum[128];
__device__ __align__(256) int    g_boff[130];
__device__ int g_is32;

// ---------------------------------------------------------------------------
__global__ void zero_kernel(int n) {
    int i = blockIdx.x * blockDim.x + threadIdx.x;
    if (i < n) { g_deg[i] = 0.0f; g_cnt[i] = 0; }
    if (i == 0) g_is32 = 0;
}

// Detect dtype from the first 2048 entries only (single block).
// int32 data read as int64 combines two random node ids -> virtually always
// out of [0,n); genuine int64 data is always in range.
__global__ void detect_kernel(const long long* __restrict__ ei64, int e, int n) {
    int lim = (e < 2048) ? e : 2048;
    int bad = 0;
    for (int i = threadIdx.x; i < lim; i += 256) {
        long long v = ei64[i];
        if ((unsigned long long)v >= (unsigned long long)n) bad = 1;
    }
    if (__syncthreads_or(bad) && threadIdx.x == 0) g_is32 = 1;
}

__global__ void edge_prep_kernel(const void* __restrict__ ei,
                                 const float* __restrict__ ew, int e, int n) {
    int i = blockIdx.x * blockDim.x + threadIdx.x;
    if (i >= e) return;
    int s, d;
    if (g_is32) {
        const int* p = (const int*)ei;
        s = p[i]; d = p[(size_t)e + i];
    } else {
        const long long* p = (const long long*)ei;
        s = (int)p[i]; d = (int)p[(size_t)e + i];
    }
    if ((unsigned)s >= (unsigned)n) s = 0;
    if ((unsigned)d >= (unsigned)n) d = 0;
    g_src[i] = s;
    g_dst[i] = d;
    g_rank[i] = atomicAdd(&g_cnt[d], 1);
    atomicAdd(&g_deg[d], ew[i]);
}

// ------- exclusive scan of padded counts -> g_ptr, fused dinv --------------
__global__ void scan1_kernel(int n) {             // 256 thr, 1024 nodes/block
    __shared__ int wsum[8];
    int b = blockIdx.x, t = threadIdx.x;
    int base = b * 1024 + t * 4;
    int c[4];
#pragma unroll
    for (int j = 0; j < 4; j++) {
        int idx = base + j;
        if (idx < n) {
            c[j] = (g_cnt[idx] + 3) & ~3;                 // pad to 4
            g_dinv[idx] = rsqrtf(1.0f + g_deg[idx]);      // deg >= 1 always
        } else c[j] = 0;
    }
    int tsum = c[0] + c[1] + c[2] + c[3];
    int lane = t & 31, w = t >> 5;
    int v = tsum;
#pragma unroll
    for (int off = 1; off < 32; off <<= 1) {
        int u = __shfl_up_sync(~0u, v, off); if (lane >= off) v += u;
    }
    if (lane == 31) wsum[w] = v;
    __syncthreads();
    if (w == 0) {
        int s = (lane < 8) ? wsum[lane] : 0;
#pragma unroll
        for (int off = 1; off < 8; off <<= 1) {
            int u = __shfl_up_sync(~0u, s, off); if (lane >= off) s += u;
        }
        if (lane < 8) wsum[lane] = s;
    }
    __syncthreads();
    int excl = v - tsum + ((w > 0) ? wsum[w - 1] : 0);
    int run = excl;
#pragma unroll
    for (int j = 0; j < 4; j++) { int idx = base + j; if (idx < n) g_ptr[idx] = run; run += c[j]; }
    if (t == 255) g_bsum[b] = excl + tsum;
}

__global__ void scan2_kernel(int nb) {            // single block, 128 thr
    __shared__ int sh[4];
    int t = threadIdx.x;
    int v = (t < nb) ? g_bsum[t] : 0;
    int lane = t & 31, w = t >> 5;
    int s = v;
#pragma unroll
    for (int off = 1; off < 32; off <<= 1) {
        int u = __shfl_up_sync(~0u, s, off); if (lane >= off) s += u;
    }
    if (lane == 31) sh[w] = s;
    __syncthreads();
    if (w == 0) {
        int x = (lane < 4) ? sh[lane] : 0;
#pragma unroll
        for (int off = 1; off < 4; off <<= 1) {
            int u = __shfl_up_sync(~0u, x, off); if (lane >= off) x += u;
        }
        if (lane < 4) sh[lane] = x;
    }
    __syncthreads();
    int excl = s - v + ((w > 0) ? sh[w - 1] : 0);
    if (t < nb) g_boff[t] = excl;
    if (t == nb - 1) g_boff[nb] = excl + v;
}

// finalize ptr, zero ONLY the pad slots (<=3 per vertex)
__global__ void scan3_kernel(int n, int nscan) {
    int i = blockIdx.x * blockDim.x + threadIdx.x;
    if (i < n) {
        int p = g_ptr[i] + g_boff[i >> 10];
        g_ptr[i] = p;
        int cnt = g_cnt[i];
        int pc  = (cnt + 3) & ~3;
        for (int j = cnt; j < pc; j++) {
            g_srcs[p + j]  = 0;
            g_norms[p + j] = 0.0f;
        }
    }
    if (i == n) g_ptr[n] = g_boff[nscan];
}

// scatter edges into sorted order; fuses norm computation
__global__ void fill_kernel(const float* __restrict__ ew, int e) {
    int i = blockIdx.x * blockDim.x + threadIdx.x;
    if (i >= e) return;
    int s = g_src[i], d = g_dst[i];
    int pos = g_ptr[d] + g_rank[i];
    g_srcs[pos]  = s;
    g_norms[pos] = g_dinv[s] * ew[i] * g_dinv[d];
}

// ---------------------------------------------------------------------------
// GEMM: H = f(X) @ W  (CIN=64), packed f32x2 FFMA. Epilogue writes fp16 H
// (gather copy) and fp32 AGG seeded with dinv^2*h (+bias for layer 2).
// ---------------------------------------------------------------------------
typedef unsigned long long u64t;
__device__ __forceinline__ u64t pack2(float lo, float hi) {
    u64t r; asm("mov.b64 %0, {%1, %2};" : "=l"(r) : "f"(lo), "f"(hi)); return r;
}
__device__ __forceinline__ void ffma2(u64t& d, u64t a, u64t b) {
    asm("fma.rn.f32x2 %0, %1, %2, %0;" : "+l"(d) : "l"(a), "l"(b));
}
__device__ __forceinline__ float2 unpack2(u64t v) {
    float2 f; asm("mov.b64 {%0, %1}, %2;" : "=f"(f.x), "=f"(f.y) : "l"(v)); return f;
}

template<int LAYER>
__global__ __launch_bounds__(128)
void gemm_kernel(const float* __restrict__ Xext,
                 const float* __restrict__ Wm,
                 const float* __restrict__ bin,
                 const float* __restrict__ bout,
                 float* __restrict__ AGGext, int n) {
    constexpr int COUT = (LAYER == 1) ? 64 : 32;
    constexpr int ROWS = (LAYER == 1) ? 32 : 64;
    constexpr int CIN  = 64;
    constexpr int CG   = COUT / 4;
    constexpr int NT   = 128;
    constexpr int XPAD = 68;

    const float* X   = (LAYER == 1) ? Xext  : g_agg1;
    __half*      Hh  = (LAYER == 1) ? g_h1h : g_h2h;
    float*       AGG = (LAYER == 1) ? g_agg1 : AGGext;

    __shared__ float Ws[CIN * COUT];
    __shared__ float xs[ROWS * XPAD];

    const int tid  = threadIdx.x;
    const int row0 = blockIdx.x * ROWS;

    for (int i = tid * 4; i < CIN * COUT; i += NT * 4)
        *(float4*)(Ws + i) = *(const float4*)(Wm + i);

    for (int i = tid; i < ROWS * (CIN / 4); i += NT) {
        int r  = i >> 4;
        int c4 = i & 15;
        int gr = row0 + r;
        float4 v = make_float4(0.f, 0.f, 0.f, 0.f);
        if (gr < n) {
            v = *(const float4*)(X + (size_t)gr * CIN + c4 * 4);
            if (LAYER == 2) {
                float4 b = *(const float4*)(bin + c4 * 4);
                v.x = fmaxf(v.x + b.x, 0.f);
                v.y = fmaxf(v.y + b.y, 0.f);
                v.z = fmaxf(v.z + b.z, 0.f);
                v.w = fmaxf(v.w + b.w, 0.f);
            }
        }
        *(float4*)(xs + r * XPAD + c4 * 4) = v;
    }
    __syncthreads();

    const int jg = tid % CG;
    const int rg = tid / CG;
    const int j0 = jg * 4;
    const int r0 = rg * 4;

    u64t acc[4][2] = {};
#pragma unroll
    for (int k = 0; k < CIN; ++k) {
        const u64t* wp = (const u64t*)(Ws + k * COUT + j0);
        u64t w01 = wp[0];
        u64t w23 = wp[1];
#pragma unroll
        for (int r = 0; r < 4; ++r) {
            float xv = xs[(r0 + r) * XPAD + k];
            u64t xx = pack2(xv, xv);
            ffma2(acc[r][0], xx, w01);
            ffma2(acc[r][1], xx, w23);
        }
    }

#pragma unroll
    for (int r = 0; r < 4; ++r) {
        int gr = row0 + r0 + r;
        if (gr >= n) continue;
        float2 a0 = unpack2(acc[r][0]);
        float2 a1 = unpack2(acc[r][1]);
        // fp16 gather copy (8B store)
        __half2 p01 = __floats2half2_rn(a0.x, a0.y);
        __half2 p23 = __floats2half2_rn(a1.x, a1.y);
        *(__half2*)(Hh + (size_t)gr * COUT + j0)     = p01;
        *(__half2*)(Hh + (size_t)gr * COUT + j0 + 2) = p23;
        // fp32 seed: exact self-loop (+ bias layer 2)
        float dv  = g_dinv[gr];
        float dv2 = dv * dv;
        float4 s = make_float4(dv2 * a0.x, dv2 * a0.y, dv2 * a1.x, dv2 * a1.y);
        if (LAYER == 2) {
            float4 b = *(const float4*)(bout + j0);
            s.x += b.x; s.y += b.y; s.z += b.z; s.w += b.w;
        }
        *(float4*)(AGG + (size_t)gr * COUT + j0) = s;
    }
}

// ---------------------------------------------------------------------------
// CSR aggregation over fp16 H. GT = COUT/8 threads per vertex; each thread
// covers 8 half-columns (16B). Accumulates in fp32 onto the seeded AGG row.
// ---------------------------------------------------------------------------
__device__ __forceinline__ void acc8(float* a, uint4 hraw, float nrm) {
    const __half2* hp = (const __half2*)&hraw;
#pragma unroll
    for (int q = 0; q < 4; q++) {
        float2 f = __half22float2(hp[q]);
        a[2 * q]     += nrm * f.x;
        a[2 * q + 1] += nrm * f.y;
    }
}

template<int LAYER>
__global__ __launch_bounds__(256)
void csr_agg_kernel(float* __restrict__ AGGext, int n) {
    constexpr int COUT = (LAYER == 1) ? 64 : 32;
    constexpr int GT   = COUT / 8;     // threads per vertex (8 / 4)
    const __half* __restrict__ H = (LAYER == 1) ? g_h1h : g_h2h;
    float* AGG = (LAYER == 1) ? g_agg1 : AGGext;

    int gi = blockIdx.x * blockDim.x + threadIdx.x;
    int v = gi / GT;
    int c = gi % GT;
    if (v >= n) return;

    int p0 = g_ptr[v], p1 = g_ptr[v + 1];

    float a[8] = {};
    const __half* Hc = H + c * 8;
    for (int k = p0; k < p1; k += 4) {
        int4   ss = *(const int4*)(g_srcs + k);
        float4 nn = *(const float4*)(g_norms + k);
        uint4 h0 = *(const uint4*)(Hc + (size_t)ss.x * COUT);
        uint4 h1 = *(const uint4*)(Hc + (size_t)ss.y * COUT);
        uint4 h2 = *(const uint4*)(Hc + (size_t)ss.z * COUT);
        uint4 h3 = *(const uint4*)(Hc + (size_t)ss.w * COUT);
        acc8(a, h0, nn.x);
        acc8(a, h1, nn.y);
        acc8(a, h2, nn.z);
        acc8(a, h3, nn.w);
    }

    float* row = AGG + (size_t)v * COUT + c * 8;
    float4 s0 = *(const float4*)(row);
    float4 s1 = *(const float4*)(row + 4);
    s0.x += a[0]; s0.y += a[1]; s0.z += a[2]; s0.w += a[3];
    s1.x += a[4]; s1.y += a[5]; s1.z += a[6]; s1.w += a[7];
    *(float4*)(row)     = s0;
    *(float4*)(row + 4) = s1;
}

// ---------------------------------------------------------------------------
extern "C" void kernel_launch(void* const* d_in, const int* in_sizes, int n_in,
                              void* d_out, int out_size) {
    const float* x   = (const float*)d_in[0];
    const void*  ei  = d_in[1];
    const float* ew  = (const float*)d_in[2];
    const float* W1  = (const float*)d_in[3];
    const float* b1  = (const float*)d_in[4];
    const float* W2  = (const float*)d_in[5];
    const float* b2  = (const float*)d_in[6];
    float*       out = (float*)d_out;

    const int n = in_sizes[0] / 64;
    const int e = in_sizes[2];

    const int T = 256;
    const int nb_n  = (n + T - 1) / T;
    const int nb_e  = (e + T - 1) / T;
    const int nscan = (n + 1023) / 1024;

    zero_kernel<<<nb_n, T>>>(n);
    detect_kernel<<<1, 256>>>((const long long*)ei, e, n);
    edge_prep_kernel<<<nb_e, T>>>(ei, ew, e, n);
    scan1_kernel<<<nscan, 256>>>(n);
    scan2_kernel<<<1, 128>>>(nscan);
    scan3_kernel<<<(n + T) / T, T>>>(n, nscan);
    fill_kernel<<<nb_e, T>>>(ew, e);

    gemm_kernel<1><<<(n + 31) / 32, 128>>>(x, W1, nullptr, nullptr, nullptr, n);
    csr_agg_kernel<1><<<(n * 8 + T - 1) / T, T>>>(nullptr, n);
    gemm_kernel<2><<<(n + 63) / 64, 128>>>(nullptr, W2, b1, b2, out, n);
    csr_agg_kernel<2><<<(n * 4 + T - 1) / T, T>>>(out, n);
}